// round 15
// baseline (speedup 1.0000x reference)
#include <cuda_runtime.h>
#include <math.h>

namespace {

constexpr int N = 64;
constexpr int WARPS = 12;
constexpr int THREADS = WARPS * 32;
constexpr int NSWEEPS = 14;        // cap; adaptive exit (L-Jacobi: ~9-11 typical)
constexpr float TAU = 6e-5f;       // apply rotation if |g_hat| > TAU * sqrt(nP*nQ)
constexpr float ANGTOL = 2.5e-4f;  // continue only while rotation matters for logm
constexpr int CPAD = 68;
constexpr unsigned FULL = 0xffffffffu;

using u64 = unsigned long long;

__device__ __forceinline__ u64 pk(float lo, float hi) {
    u64 r; asm("mov.b64 %0,{%1,%2};" : "=l"(r) : "f"(lo), "f"(hi)); return r;
}
__device__ __forceinline__ void upk(u64 v, float& lo, float& hi) {
    asm("mov.b64 {%0,%1},%2;" : "=f"(lo), "=f"(hi) : "l"(v));
}
__device__ __forceinline__ u64 mul2(u64 a, u64 b) {
    u64 r; asm("mul.rn.f32x2 %0,%1,%2;" : "=l"(r) : "l"(a), "l"(b)); return r;
}
__device__ __forceinline__ u64 fma2(u64 a, u64 b, u64 c) {
    u64 r; asm("fma.rn.f32x2 %0,%1,%2,%3;" : "=l"(r) : "l"(a), "l"(b), "l"(c)); return r;
}
__device__ __forceinline__ u64 add2(u64 a, u64 b) {
    u64 r; asm("add.rn.f32x2 %0,%1,%2;" : "=l"(r) : "l"(a), "l"(b)); return r;
}
__device__ __forceinline__ float psum(u64 v) {
    float lo, hi; upk(v, lo, hi); return lo + hi;
}
__device__ __forceinline__ float psum4(u64 a, u64 b, u64 c, u64 d) {
    return psum(add2(add2(a, b), add2(c, d)));
}

// Rotation parameters for ordered pair (p, q) — R11 form.
__device__ __forceinline__ void params(float nP, float nQ, float sP, float sQ,
                                       float gh, float& alpha, float& beta,
                                       float& c, float& rc2, bool& any) {
    float ga = sP * sQ * gh;
    float nPa = sP * sP * nP, nQa = sQ * sQ * nQ;
    float zeta = __fdividef(nQa - nPa, 2.0f * ga);
    float tt = __fdividef(copysignf(1.0f, zeta),
                          fabsf(zeta) + sqrtf(fmaf(zeta, zeta, 1.0f)));
    c = rsqrtf(fmaf(tt, tt, 1.0f));
    rc2 = fmaf(tt, tt, 1.0f);
    float r = __fdividef(sQ, sP);
    alpha = tt * r;                // P' = P - alpha*Q
    beta = __fdividef(tt, r);      // Q' = Q + beta*P
    if (fabsf(tt) * fabsf(nQa - nPa) > ANGTOL * (nQa + nPa)) any = true;
}

__global__ void __launch_bounds__(THREADS, 1)
logm_warpjac(const float* __restrict__ in, float* __restrict__ out, int nmat) {
    extern __shared__ float sm[];

    const int lane = threadIdx.x & 31;
    const int wid = threadIdx.x >> 5;
    const int m = blockIdx.x * WARPS + wid;
    if (m >= nmat) return;                      // whole-warp uniform; no CTA syncs

    float* Wsh = sm + wid * (N * CPAD);
    const float* A = in + (long long)m * (N * N);

    // Lane holds 2 full columns (2*lane, 2*lane+1) as 32 packed f32x2 each.
    u64 T[32], B[32];
    {
        const float4* p = reinterpret_cast<const float4*>(A + (2 * lane) * N);
        const float4* q = reinterpret_cast<const float4*>(A + (2 * lane + 1) * N);
#pragma unroll
        for (int k = 0; k < 16; k++) {
            float4 v = p[k];
            T[2 * k] = pk(v.x, v.y); T[2 * k + 1] = pk(v.z, v.w);
            float4 w = q[k];
            B[2 * k] = pk(w.x, w.y); B[2 * k + 1] = pk(w.z, w.w);
        }
    }

    // ===== Cholesky in registers: A -> L (in place), right-looking =====
    // Gram of L's columns is L^T L with kappa = kappa(A) (not kappa(A)^2),
    // halving the Jacobi sweep count. Pivot column staged via shared.
    {
        u64* stage = reinterpret_cast<u64*>(Wsh);   // 64 floats
        for (int j = 0; j < N; j++) {
            const int owner = j >> 1;
            const bool odd = j & 1;
            // broadcast pivot a_jj (column j, row j)
            u64 pr = odd ? B[j >> 1] : T[j >> 1];
            float plo, phi; upk(pr, plo, phi);
            float pv = __shfl_sync(FULL, odd ? phi : plo, owner);
            float rp = rsqrtf(pv);
            float rp2 = rp * rp;
            // owner stages raw column j
            if (lane == owner) {
                if (odd) {
#pragma unroll
                    for (int k = 0; k < 32; k++) stage[k] = B[k];
                } else {
#pragma unroll
                    for (int k = 0; k < 32; k++) stage[k] = T[k];
                }
            }
            __syncwarp();
            // per-lane multipliers: rows 2*lane, 2*lane+1 of column j
            float2 myp = *reinterpret_cast<float2*>(Wsh + 2 * lane);
            u64 mfT = pk(-myp.x * rp2, -myp.x * rp2);
            u64 mfB = pk(-myp.y * rp2, -myp.y * rp2);
            const bool updT = (2 * lane) > j;
            const bool updB = (2 * lane + 1) > j;
#pragma unroll
            for (int k = 0; k < 32; k++) {
                u64 lk = stage[k];                 // broadcast LDS
                if (updT) T[k] = fma2(lk, mfT, T[k]);
                if (updB) B[k] = fma2(lk, mfB, B[k]);
            }
            // owner finalizes column j: l_j = a_j * rp
            if (lane == owner) {
                u64 rpp = pk(rp, rp);
                if (odd) {
#pragma unroll
                    for (int k = 0; k < 32; k++) B[k] = mul2(B[k], rpp);
                } else {
#pragma unroll
                    for (int k = 0; k < 32; k++) T[k] = mul2(T[k], rpp);
                }
            }
            __syncwarp();
        }
    }

    float sT = 1.0f, sB = 1.0f;     // column scales (fast rotations)
    float nT = 0.0f, nB = 0.0f;     // scaled squared norms: actual = s^2 * n

    const int up = (lane + 31) & 31;   // lane-1 mod 32
    const int dn = (lane + 1) & 31;    // lane+1 mod 32
    const bool l0 = (lane == 0);

    for (int sweep = 0; sweep < NSWEEPS; sweep++) {
        // fold scales + exact norm refresh
        {
            u64 s1 = pk(sT, sT), s2 = pk(sB, sB);
            u64 a0 = pk(0.f, 0.f), a1 = a0, a2 = a0, a3 = a0;
            u64 b0 = a0, b1 = a0, b2a = a0, b3 = a0;
#pragma unroll
            for (int k = 0; k < 8; k++) {
                T[4 * k]     = mul2(T[4 * k], s1);     T[4 * k + 1] = mul2(T[4 * k + 1], s1);
                T[4 * k + 2] = mul2(T[4 * k + 2], s1); T[4 * k + 3] = mul2(T[4 * k + 3], s1);
                B[4 * k]     = mul2(B[4 * k], s2);     B[4 * k + 1] = mul2(B[4 * k + 1], s2);
                B[4 * k + 2] = mul2(B[4 * k + 2], s2); B[4 * k + 3] = mul2(B[4 * k + 3], s2);
                a0 = fma2(T[4 * k],     T[4 * k],     a0);
                a1 = fma2(T[4 * k + 1], T[4 * k + 1], a1);
                a2 = fma2(T[4 * k + 2], T[4 * k + 2], a2);
                a3 = fma2(T[4 * k + 3], T[4 * k + 3], a3);
                b0 = fma2(B[4 * k],     B[4 * k],     b0);
                b1 = fma2(B[4 * k + 1], B[4 * k + 1], b1);
                b2a = fma2(B[4 * k + 2], B[4 * k + 2], b2a);
                b3 = fma2(B[4 * k + 3], B[4 * k + 3], b3);
            }
            sT = 1.0f; sB = 1.0f;
            nT = psum4(a0, a1, a2, a3);
            nB = psum4(b0, b1, b2a, b3);
        }
        bool any = false;

        for (int it = 0; it < 32; it++) {
            // ============ even round: local pair (T, B) ============
            {
                u64 g0 = pk(0.f, 0.f), g1 = g0, g2 = g0, g3 = g0;
#pragma unroll
                for (int k = 0; k < 8; k++) {
                    g0 = fma2(T[4 * k],     B[4 * k],     g0);
                    g1 = fma2(T[4 * k + 1], B[4 * k + 1], g1);
                    g2 = fma2(T[4 * k + 2], B[4 * k + 2], g2);
                    g3 = fma2(T[4 * k + 3], B[4 * k + 3], g3);
                }
                float gh = psum4(g0, g1, g2, g3);

                float alpha = 0.f, beta = 0.f, c = 1.f, rc2 = 1.f;
                if (fabsf(gh) > TAU * sqrtf(nT * nB)) {
                    params(nT, nB, sT, sB, gh, alpha, beta, c, rc2, any);
                }
                // outputs swapped: top <- Q', bottom <- P'  (skip => pure swap)
                u64 b2 = pk(beta, beta), na2 = pk(-alpha, -alpha);
#pragma unroll
                for (int k = 0; k < 32; k++) {
                    u64 t0 = T[k];
                    T[k] = fma2(t0, b2, B[k]);     // Q' = B + beta*T
                    B[k] = fma2(B[k], na2, t0);    // P' = T - alpha*B
                }
                float nTn = (nB + beta * gh) * rc2;
                float nBn = (nT - alpha * gh) * rc2;
                float sTn = sB * c, sBn = sT * c;
                sT = sTn; sB = sBn; nT = nTn; nB = nBn;
            }
            // ==== odd round: in-place wrap exchange; pair (P=B_{u-1}, Q=T_u) ====
            {
                u64 g0 = pk(0.f, 0.f), g1 = g0, g2 = g0, g3 = g0;
#pragma unroll
                for (int k = 0; k < 8; k++) {
                    B[4 * k]     = __shfl_sync(FULL, B[4 * k],     up);
                    B[4 * k + 1] = __shfl_sync(FULL, B[4 * k + 1], up);
                    B[4 * k + 2] = __shfl_sync(FULL, B[4 * k + 2], up);
                    B[4 * k + 3] = __shfl_sync(FULL, B[4 * k + 3], up);
                    g0 = fma2(B[4 * k],     T[4 * k],     g0);
                    g1 = fma2(B[4 * k + 1], T[4 * k + 1], g1);
                    g2 = fma2(B[4 * k + 2], T[4 * k + 2], g2);
                    g3 = fma2(B[4 * k + 3], T[4 * k + 3], g3);
                }
                float gh = psum4(g0, g1, g2, g3);
                float nP = __shfl_sync(FULL, nB, up);
                float sP = __shfl_sync(FULL, sB, up);

                float alpha = 0.f, beta = 0.f, c = 1.f, rc2 = 1.f;
                if (!l0 && fabsf(gh) > TAU * sqrtf(nP * nT)) {
                    params(nP, nT, sP, sT, gh, alpha, beta, c, rc2, any);
                }
                u64 b2 = pk(beta, beta), na2 = pk(-alpha, -alpha);
#pragma unroll
                for (int k = 0; k < 32; k++) {
                    u64 q = fma2(B[k], b2, T[k]);      // Q' = T + beta*B
                    u64 p = fma2(T[k], na2, B[k]);     // P' = B - alpha*T
                    u64 ship = l0 ? B[k] : q;          // lane0 forwards parked B_31
                    u64 rcv = __shfl_sync(FULL, ship, dn);
                    if (lane >= 1) T[k] = p;
                    B[k] = rcv;
                }
                float shipN = l0 ? nP : (nT + beta * gh) * rc2;
                float shipS = l0 ? sP : c * sT;
                float rN = __shfl_sync(FULL, shipN, dn);
                float rS = __shfl_sync(FULL, shipS, dn);
                if (lane >= 1) { nT = (nP - alpha * gh) * rc2; sT = c * sP; }
                nB = rN; sB = rS;
            }
        }
        if (!__any_sync(FULL, any)) break;
    }

    // ---- finalize: W = U*Sigma (columns of rotated L); lambda = ||w||^2 ----
    float ssT, ssB;
    {
        u64 s1 = pk(sT, sT), s2 = pk(sB, sB);
        u64 a0 = pk(0.f, 0.f), a1 = a0, b0 = a0, b1 = a0;
#pragma unroll
        for (int k = 0; k < 16; k++) {
            T[2 * k] = mul2(T[2 * k], s1); T[2 * k + 1] = mul2(T[2 * k + 1], s1);
            B[2 * k] = mul2(B[2 * k], s2); B[2 * k + 1] = mul2(B[2 * k + 1], s2);
            a0 = fma2(T[2 * k], T[2 * k], a0); a1 = fma2(T[2 * k + 1], T[2 * k + 1], a1);
            b0 = fma2(B[2 * k], B[2 * k], b0); b1 = fma2(B[2 * k + 1], B[2 * k + 1], b1);
        }
        ssT = psum(a0) + psum(a1);
        ssB = psum(b0) + psum(b1);
    }
    {
        u64* c0 = reinterpret_cast<u64*>(Wsh + (2 * lane) * CPAD);
        u64* c1 = reinterpret_cast<u64*>(Wsh + (2 * lane + 1) * CPAD);
#pragma unroll
        for (int k = 0; k < 32; k++) { c0[k] = T[k]; c1[k] = B[k]; }
        // lambda = ss (sigma^2); dsc = log(lambda + eps) / lambda
        float s0 = fmaxf(ssT, 1e-30f);
        Wsh[(2 * lane) * CPAD + 64] = __fdividef(logf(s0 + 1e-9f), s0);
        float s1 = fmaxf(ssB, 1e-30f);
        Wsh[(2 * lane + 1) * CPAD + 64] = __fdividef(logf(s1 + 1e-9f), s1);
    }
    __syncwarp();

    // ---- out = sum_c dsc_c * w_c w_c^T : lane computes rows 2*lane, 2*lane+1 ----
    {
        u64 a0[32], a1[32];
#pragma unroll
        for (int k = 0; k < 32; k++) { a0[k] = pk(0.f, 0.f); a1[k] = pk(0.f, 0.f); }
#pragma unroll 4
        for (int cidx = 0; cidx < N; cidx++) {
            const float* col = Wsh + cidx * CPAD;
            float dc = col[64];
            float2 wi = *reinterpret_cast<const float2*>(col + 2 * lane);
            float u0 = wi.x * dc, u1 = wi.y * dc;
            u64 u02 = pk(u0, u0), u12 = pk(u1, u1);
#pragma unroll
            for (int k = 0; k < 16; k++) {
                ulonglong2 q = *reinterpret_cast<const ulonglong2*>(col + 4 * k);
                a0[2 * k]     = fma2(u02, q.x, a0[2 * k]);
                a0[2 * k + 1] = fma2(u02, q.y, a0[2 * k + 1]);
                a1[2 * k]     = fma2(u12, q.x, a1[2 * k]);
                a1[2 * k + 1] = fma2(u12, q.y, a1[2 * k + 1]);
            }
        }
        float* o0 = out + (long long)m * (N * N) + (2 * lane) * N;
        float* o1 = o0 + N;
#pragma unroll
        for (int k = 0; k < 16; k++) {
            ulonglong2 v0; v0.x = a0[2 * k]; v0.y = a0[2 * k + 1];
            *reinterpret_cast<ulonglong2*>(o0 + 4 * k) = v0;
            ulonglong2 v1; v1.x = a1[2 * k]; v1.y = a1[2 * k + 1];
            *reinterpret_cast<ulonglong2*>(o1 + 4 * k) = v1;
        }
    }
}

}  // namespace

extern "C" void kernel_launch(void* const* d_in, const int* in_sizes, int n_in,
                              void* d_out, int out_size) {
    const float* in = (const float*)d_in[0];
    float* out = (float*)d_out;
    const int nmat = in_sizes[0] / (N * N);   // 8192
    const int smem = WARPS * N * CPAD * (int)sizeof(float);   // 208,896 B
    cudaFuncSetAttribute(logm_warpjac, cudaFuncAttributeMaxDynamicSharedMemorySize, smem);
    const int grid = (nmat + WARPS - 1) / WARPS;
    logm_warpjac<<<grid, THREADS, smem>>>(in, out, nmat);
}

// round 16
// speedup vs baseline: 6.2641x; 6.2641x over previous
#include <cuda_runtime.h>
#include <math.h>

namespace {

constexpr int N = 64;
constexpr int WARPS = 12;
constexpr int THREADS = WARPS * 32;
constexpr int NSWEEPS = 14;        // cap; adaptive exit (L-Jacobi: ~9-11 typical)
constexpr float TAU = 6e-5f;       // apply rotation if |g_hat| > TAU * sqrt(nP*nQ)
constexpr float ANGTOL = 2.5e-4f;  // continue only while rotation matters for logm
constexpr int CPAD = 68;
constexpr unsigned FULL = 0xffffffffu;

using u64 = unsigned long long;

__device__ __forceinline__ u64 pk(float lo, float hi) {
    u64 r; asm("mov.b64 %0,{%1,%2};" : "=l"(r) : "f"(lo), "f"(hi)); return r;
}
__device__ __forceinline__ void upk(u64 v, float& lo, float& hi) {
    asm("mov.b64 {%0,%1},%2;" : "=f"(lo), "=f"(hi) : "l"(v));
}
__device__ __forceinline__ u64 mul2(u64 a, u64 b) {
    u64 r; asm("mul.rn.f32x2 %0,%1,%2;" : "=l"(r) : "l"(a), "l"(b)); return r;
}
__device__ __forceinline__ u64 fma2(u64 a, u64 b, u64 c) {
    u64 r; asm("fma.rn.f32x2 %0,%1,%2,%3;" : "=l"(r) : "l"(a), "l"(b), "l"(c)); return r;
}
__device__ __forceinline__ u64 add2(u64 a, u64 b) {
    u64 r; asm("add.rn.f32x2 %0,%1,%2;" : "=l"(r) : "l"(a), "l"(b)); return r;
}
__device__ __forceinline__ float psum(u64 v) {
    float lo, hi; upk(v, lo, hi); return lo + hi;
}
__device__ __forceinline__ float psum4(u64 a, u64 b, u64 c, u64 d) {
    return psum(add2(add2(a, b), add2(c, d)));
}

// Rotation parameters for ordered pair (p, q) — R11 form.
__device__ __forceinline__ void params(float nP, float nQ, float sP, float sQ,
                                       float gh, float& alpha, float& beta,
                                       float& c, float& rc2, bool& any) {
    float ga = sP * sQ * gh;
    float nPa = sP * sP * nP, nQa = sQ * sQ * nQ;
    float zeta = __fdividef(nQa - nPa, 2.0f * ga);
    float tt = __fdividef(copysignf(1.0f, zeta),
                          fabsf(zeta) + sqrtf(fmaf(zeta, zeta, 1.0f)));
    c = rsqrtf(fmaf(tt, tt, 1.0f));
    rc2 = fmaf(tt, tt, 1.0f);
    float r = __fdividef(sQ, sP);
    alpha = tt * r;                // P' = P - alpha*Q
    beta = __fdividef(tt, r);      // Q' = Q + beta*P
    if (fabsf(tt) * fabsf(nQa - nPa) > ANGTOL * (nQa + nPa)) any = true;
}

__global__ void __launch_bounds__(THREADS, 1)
logm_warpjac(const float* __restrict__ in, float* __restrict__ out, int nmat) {
    extern __shared__ float sm[];

    const int lane = threadIdx.x & 31;
    const int wid = threadIdx.x >> 5;
    const int m = blockIdx.x * WARPS + wid;
    if (m >= nmat) return;                      // whole-warp uniform; no CTA syncs

    float* Wsh = sm + wid * (N * CPAD);
    const float* A = in + (long long)m * (N * N);

    // Lane holds 2 full columns (2*lane, 2*lane+1) as 32 packed f32x2 each.
    u64 T[32], B[32];
    {
        const float4* p = reinterpret_cast<const float4*>(A + (2 * lane) * N);
        const float4* q = reinterpret_cast<const float4*>(A + (2 * lane + 1) * N);
#pragma unroll
        for (int k = 0; k < 16; k++) {
            float4 v = p[k];
            T[2 * k] = pk(v.x, v.y); T[2 * k + 1] = pk(v.z, v.w);
            float4 w = q[k];
            B[2 * k] = pk(w.x, w.y); B[2 * k + 1] = pk(w.z, w.w);
        }
    }

    // ===== Cholesky in registers: A -> L (in place), right-looking =====
    // Gram of L's columns is L^T L with kappa = kappa(A) (not kappa(A)^2),
    // roughly halving Jacobi sweeps. Pivot column staged through shared;
    // pivot value is read from the STAGED column (Wsh[j]) — never via a
    // runtime-indexed register access (that spills T/B to local).
    {
        u64* stage = reinterpret_cast<u64*>(Wsh);   // 64 floats
        for (int j = 0; j < N; j++) {
            const int owner = j >> 1;
            const bool odd = j & 1;
            // owner stages raw (updated) column j — static register indices only
            if (lane == owner) {
                if (odd) {
#pragma unroll
                    for (int k = 0; k < 32; k++) stage[k] = B[k];
                } else {
#pragma unroll
                    for (int k = 0; k < 32; k++) stage[k] = T[k];
                }
            }
            __syncwarp();
            // pivot from the staged column (shared broadcast, runtime j is fine)
            float pv = Wsh[j];
            float rp = rsqrtf(pv);
            float rp2 = rp * rp;
            // per-lane multipliers: rows of column j at this lane's column indices
            float2 myp = *reinterpret_cast<float2*>(Wsh + 2 * lane);
            u64 mfT = pk(-myp.x * rp2, -myp.x * rp2);
            u64 mfB = pk(-myp.y * rp2, -myp.y * rp2);
            const bool updT = (2 * lane) > j;
            const bool updB = (2 * lane + 1) > j;
#pragma unroll
            for (int k = 0; k < 32; k++) {
                u64 lk = stage[k];                 // broadcast LDS
                if (updT) T[k] = fma2(lk, mfT, T[k]);
                if (updB) B[k] = fma2(lk, mfB, B[k]);
            }
            // owner finalizes column j: l_j = a_j * rp
            if (lane == owner) {
                u64 rpp = pk(rp, rp);
                if (odd) {
#pragma unroll
                    for (int k = 0; k < 32; k++) B[k] = mul2(B[k], rpp);
                } else {
#pragma unroll
                    for (int k = 0; k < 32; k++) T[k] = mul2(T[k], rpp);
                }
            }
            __syncwarp();
        }
    }

    float sT = 1.0f, sB = 1.0f;     // column scales (fast rotations)
    float nT = 0.0f, nB = 0.0f;     // scaled squared norms: actual = s^2 * n

    const int up = (lane + 31) & 31;   // lane-1 mod 32
    const int dn = (lane + 1) & 31;    // lane+1 mod 32
    const bool l0 = (lane == 0);

    for (int sweep = 0; sweep < NSWEEPS; sweep++) {
        // fold scales + exact norm refresh
        {
            u64 s1 = pk(sT, sT), s2 = pk(sB, sB);
            u64 a0 = pk(0.f, 0.f), a1 = a0, a2 = a0, a3 = a0;
            u64 b0 = a0, b1 = a0, b2a = a0, b3 = a0;
#pragma unroll
            for (int k = 0; k < 8; k++) {
                T[4 * k]     = mul2(T[4 * k], s1);     T[4 * k + 1] = mul2(T[4 * k + 1], s1);
                T[4 * k + 2] = mul2(T[4 * k + 2], s1); T[4 * k + 3] = mul2(T[4 * k + 3], s1);
                B[4 * k]     = mul2(B[4 * k], s2);     B[4 * k + 1] = mul2(B[4 * k + 1], s2);
                B[4 * k + 2] = mul2(B[4 * k + 2], s2); B[4 * k + 3] = mul2(B[4 * k + 3], s2);
                a0 = fma2(T[4 * k],     T[4 * k],     a0);
                a1 = fma2(T[4 * k + 1], T[4 * k + 1], a1);
                a2 = fma2(T[4 * k + 2], T[4 * k + 2], a2);
                a3 = fma2(T[4 * k + 3], T[4 * k + 3], a3);
                b0 = fma2(B[4 * k],     B[4 * k],     b0);
                b1 = fma2(B[4 * k + 1], B[4 * k + 1], b1);
                b2a = fma2(B[4 * k + 2], B[4 * k + 2], b2a);
                b3 = fma2(B[4 * k + 3], B[4 * k + 3], b3);
            }
            sT = 1.0f; sB = 1.0f;
            nT = psum4(a0, a1, a2, a3);
            nB = psum4(b0, b1, b2a, b3);
        }
        bool any = false;

        for (int it = 0; it < 32; it++) {
            // ============ even round: local pair (T, B) ============
            {
                u64 g0 = pk(0.f, 0.f), g1 = g0, g2 = g0, g3 = g0;
#pragma unroll
                for (int k = 0; k < 8; k++) {
                    g0 = fma2(T[4 * k],     B[4 * k],     g0);
                    g1 = fma2(T[4 * k + 1], B[4 * k + 1], g1);
                    g2 = fma2(T[4 * k + 2], B[4 * k + 2], g2);
                    g3 = fma2(T[4 * k + 3], B[4 * k + 3], g3);
                }
                float gh = psum4(g0, g1, g2, g3);

                float alpha = 0.f, beta = 0.f, c = 1.f, rc2 = 1.f;
                if (fabsf(gh) > TAU * sqrtf(nT * nB)) {
                    params(nT, nB, sT, sB, gh, alpha, beta, c, rc2, any);
                }
                // outputs swapped: top <- Q', bottom <- P'  (skip => pure swap)
                u64 b2 = pk(beta, beta), na2 = pk(-alpha, -alpha);
#pragma unroll
                for (int k = 0; k < 32; k++) {
                    u64 t0 = T[k];
                    T[k] = fma2(t0, b2, B[k]);     // Q' = B + beta*T
                    B[k] = fma2(B[k], na2, t0);    // P' = T - alpha*B
                }
                float nTn = (nB + beta * gh) * rc2;
                float nBn = (nT - alpha * gh) * rc2;
                float sTn = sB * c, sBn = sT * c;
                sT = sTn; sB = sBn; nT = nTn; nB = nBn;
            }
            // ==== odd round: in-place wrap exchange; pair (P=B_{u-1}, Q=T_u) ====
            {
                u64 g0 = pk(0.f, 0.f), g1 = g0, g2 = g0, g3 = g0;
#pragma unroll
                for (int k = 0; k < 8; k++) {
                    B[4 * k]     = __shfl_sync(FULL, B[4 * k],     up);
                    B[4 * k + 1] = __shfl_sync(FULL, B[4 * k + 1], up);
                    B[4 * k + 2] = __shfl_sync(FULL, B[4 * k + 2], up);
                    B[4 * k + 3] = __shfl_sync(FULL, B[4 * k + 3], up);
                    g0 = fma2(B[4 * k],     T[4 * k],     g0);
                    g1 = fma2(B[4 * k + 1], T[4 * k + 1], g1);
                    g2 = fma2(B[4 * k + 2], T[4 * k + 2], g2);
                    g3 = fma2(B[4 * k + 3], T[4 * k + 3], g3);
                }
                float gh = psum4(g0, g1, g2, g3);
                float nP = __shfl_sync(FULL, nB, up);
                float sP = __shfl_sync(FULL, sB, up);

                float alpha = 0.f, beta = 0.f, c = 1.f, rc2 = 1.f;
                if (!l0 && fabsf(gh) > TAU * sqrtf(nP * nT)) {
                    params(nP, nT, sP, sT, gh, alpha, beta, c, rc2, any);
                }
                u64 b2 = pk(beta, beta), na2 = pk(-alpha, -alpha);
#pragma unroll
                for (int k = 0; k < 32; k++) {
                    u64 q = fma2(B[k], b2, T[k]);      // Q' = T + beta*B
                    u64 p = fma2(T[k], na2, B[k]);     // P' = B - alpha*T
                    u64 ship = l0 ? B[k] : q;          // lane0 forwards parked B_31
                    u64 rcv = __shfl_sync(FULL, ship, dn);
                    if (lane >= 1) T[k] = p;
                    B[k] = rcv;
                }
                float shipN = l0 ? nP : (nT + beta * gh) * rc2;
                float shipS = l0 ? sP : c * sT;
                float rN = __shfl_sync(FULL, shipN, dn);
                float rS = __shfl_sync(FULL, shipS, dn);
                if (lane >= 1) { nT = (nP - alpha * gh) * rc2; sT = c * sP; }
                nB = rN; sB = rS;
            }
        }
        if (!__any_sync(FULL, any)) break;
    }

    // ---- finalize: W = U*Sigma (columns of rotated L); lambda = ||w||^2 ----
    float ssT, ssB;
    {
        u64 s1 = pk(sT, sT), s2 = pk(sB, sB);
        u64 a0 = pk(0.f, 0.f), a1 = a0, b0 = a0, b1 = a0;
#pragma unroll
        for (int k = 0; k < 16; k++) {
            T[2 * k] = mul2(T[2 * k], s1); T[2 * k + 1] = mul2(T[2 * k + 1], s1);
            B[2 * k] = mul2(B[2 * k], s2); B[2 * k + 1] = mul2(B[2 * k + 1], s2);
            a0 = fma2(T[2 * k], T[2 * k], a0); a1 = fma2(T[2 * k + 1], T[2 * k + 1], a1);
            b0 = fma2(B[2 * k], B[2 * k], b0); b1 = fma2(B[2 * k + 1], B[2 * k + 1], b1);
        }
        ssT = psum(a0) + psum(a1);
        ssB = psum(b0) + psum(b1);
    }
    {
        u64* c0 = reinterpret_cast<u64*>(Wsh + (2 * lane) * CPAD);
        u64* c1 = reinterpret_cast<u64*>(Wsh + (2 * lane + 1) * CPAD);
#pragma unroll
        for (int k = 0; k < 32; k++) { c0[k] = T[k]; c1[k] = B[k]; }
        // lambda = ss (sigma^2 of L); dsc = log(lambda + eps) / lambda
        float s0 = fmaxf(ssT, 1e-30f);
        Wsh[(2 * lane) * CPAD + 64] = __fdividef(logf(s0 + 1e-9f), s0);
        float s1 = fmaxf(ssB, 1e-30f);
        Wsh[(2 * lane + 1) * CPAD + 64] = __fdividef(logf(s1 + 1e-9f), s1);
    }
    __syncwarp();

    // ---- out = sum_c dsc_c * w_c w_c^T : lane computes rows 2*lane, 2*lane+1 ----
    {
        u64 a0[32], a1[32];
#pragma unroll
        for (int k = 0; k < 32; k++) { a0[k] = pk(0.f, 0.f); a1[k] = pk(0.f, 0.f); }
#pragma unroll 4
        for (int cidx = 0; cidx < N; cidx++) {
            const float* col = Wsh + cidx * CPAD;
            float dc = col[64];
            float2 wi = *reinterpret_cast<const float2*>(col + 2 * lane);
            float u0 = wi.x * dc, u1 = wi.y * dc;
            u64 u02 = pk(u0, u0), u12 = pk(u1, u1);
#pragma unroll
            for (int k = 0; k < 16; k++) {
                ulonglong2 q = *reinterpret_cast<const ulonglong2*>(col + 4 * k);
                a0[2 * k]     = fma2(u02, q.x, a0[2 * k]);
                a0[2 * k + 1] = fma2(u02, q.y, a0[2 * k + 1]);
                a1[2 * k]     = fma2(u12, q.x, a1[2 * k]);
                a1[2 * k + 1] = fma2(u12, q.y, a1[2 * k + 1]);
            }
        }
        float* o0 = out + (long long)m * (N * N) + (2 * lane) * N;
        float* o1 = o0 + N;
#pragma unroll
        for (int k = 0; k < 16; k++) {
            ulonglong2 v0; v0.x = a0[2 * k]; v0.y = a0[2 * k + 1];
            *reinterpret_cast<ulonglong2*>(o0 + 4 * k) = v0;
            ulonglong2 v1; v1.x = a1[2 * k]; v1.y = a1[2 * k + 1];
            *reinterpret_cast<ulonglong2*>(o1 + 4 * k) = v1;
        }
    }
}

}  // namespace

extern "C" void kernel_launch(void* const* d_in, const int* in_sizes, int n_in,
                              void* d_out, int out_size) {
    const float* in = (const float*)d_in[0];
    float* out = (float*)d_out;
    const int nmat = in_sizes[0] / (N * N);   // 8192
    const int smem = WARPS * N * CPAD * (int)sizeof(float);   // 208,896 B
    cudaFuncSetAttribute(logm_warpjac, cudaFuncAttributeMaxDynamicSharedMemorySize, smem);
    const int grid = (nmat + WARPS - 1) / WARPS;
    logm_warpjac<<<grid, THREADS, smem>>>(in, out, nmat);
}